// round 4
// baseline (speedup 1.0000x reference)
#include <cuda_runtime.h>

#define BATCH 256
#define TSTEPS 4096
#define D 64
#define H 192
#define NCLS 10
#define BETA 0.9f

__global__ __launch_bounds__(H, 2)
void lsnn_kernel(const float* __restrict__ x,
                 const float* __restrict__ enc_w,
                 const float* __restrict__ enc_b,
                 const float* __restrict__ ro_w,
                 const float* __restrict__ ro_b,
                 const float* __restrict__ A,
                 const float* __restrict__ Bv,
                 float* __restrict__ out,     // [BATCH, NCLS] or null
                 float* __restrict__ spk)     // [BATCH, TSTEPS, H]
{
    __shared__ __align__(16) float sbuf[2][D];   // ping-pong SSM state
    __shared__ float At[D][D];                   // A transposed: At[k][i] = A[i][k]
    __shared__ float srate[H];

    const int b = blockIdx.x;
    const int tid = threadIdx.x;

    // enc_w row for this neuron, fp32, register-resident
    float w[D];
    {
        const float4* wrow = reinterpret_cast<const float4*>(enc_w + tid * D);
#pragma unroll
        for (int j = 0; j < D / 4; j++) {
            float4 f = wrow[j];
            w[4 * j + 0] = f.x; w[4 * j + 1] = f.y;
            w[4 * j + 2] = f.z; w[4 * j + 3] = f.w;
        }
    }
    const float eb = enc_b[tid];

    // A into shared, transposed (conflict-free reads: At[k][tid])
    for (int idx = tid; idx < D * D; idx += H) {
        int i = idx / D, k = idx % D;
        At[k][i] = A[idx];
    }
    float Bi = 0.f;
    if (tid < D) {
        Bi = Bv[tid];
        sbuf[0][tid] = 0.f;
        sbuf[1][tid] = 0.f;
    }

    float mem = 0.f;
    float rate = 0.f;
    float* spkb = spk + (size_t)b * TSTEPS * H + tid;
    const float* xb = x + (size_t)b * TSTEPS;

    __syncthreads();

    int p = 0;
    float4 u4 = make_float4(0.f, 0.f, 0.f, 0.f);

    for (int t = 0; t < TSTEPS; t++) {
        if ((t & 3) == 0) u4 = *reinterpret_cast<const float4*>(xb + t);
        float u = u4.x;
        u4.x = u4.y; u4.y = u4.z; u4.z = u4.w;

        // ---- phase 1: state' = A @ state + B*u (threads 0..63) ----
        // cuBLAS SGEMM emulation: single accumulator, sequential k, FFMA chain.
        if (tid < D) {
            float acc = 0.f;
            const float* s = sbuf[p];
#pragma unroll
            for (int k = 0; k < D; k++)
                acc = __fmaf_rn(At[k][tid], s[k], acc);
            // XLA:GPU fusion contracts dot + u*B  ->  fma(u, B[i], dot)
            float ns = __fmaf_rn(Bi, u, acc);
            sbuf[p ^ 1][tid] = ns;
        }
        __syncthreads();

        // ---- phase 2: cur = enc_w @ state' + b ; LIF (all 192 threads) ----
        {
            float acc = 0.f;
            const float* s = sbuf[p ^ 1];
#pragma unroll
            for (int k = 0; k < D; k++)
                acc = __fmaf_rn(w[k], s[k], acc);
            float cur = __fadd_rn(acc, eb);

            // XLA:GPU fusion contracts 0.9*mem + cur -> fma(0.9, mem, cur)
            mem = __fmaf_rn(BETA, mem, cur);
            float s1 = (__fadd_rn(mem, -1.0f) > 0.f) ? 1.f : 0.f;
            rate = __fadd_rn(rate, s1);
            spkb[(size_t)t * H] = s1;
            mem = __fmul_rn(mem, __fadd_rn(1.0f, -s1));
        }
        p ^= 1;
    }

    // ---- readout: out = (rate/T) @ ro_w^T + ro_b ----
    // mean is exact (integer sum * 2^-12); gemm emulated sequential-k fmaf.
    srate[tid] = __fmul_rn(rate, 1.0f / (float)TSTEPS);
    __syncthreads();
    if (tid < NCLS && out != nullptr) {
        float acc = 0.f;
        const float* rw = ro_w + tid * H;
#pragma unroll
        for (int h = 0; h < H; h++)
            acc = __fmaf_rn(rw[h], srate[h], acc);
        out[b * NCLS + tid] = __fadd_rn(acc, ro_b[tid]);
    }
}

extern "C" void kernel_launch(void* const* d_in, const int* in_sizes, int n_in,
                              void* d_out, int out_size) {
    const float* x     = (const float*)d_in[0];
    const float* enc_w = (const float*)d_in[1];
    const float* enc_b = (const float*)d_in[2];
    const float* ro_w  = (const float*)d_in[3];
    const float* ro_b  = (const float*)d_in[4];
    const float* A     = (const float*)d_in[5];
    const float* Bv    = (const float*)d_in[6];

    float* base = (float*)d_out;
    const long long spkElems = (long long)BATCH * TSTEPS * H;   // 201326592
    const long long outElems = (long long)BATCH * NCLS;          // 2560

    float* outp;
    float* spkp;
    if ((long long)out_size >= spkElems + outElems) {
        outp = base;
        spkp = base + outElems;
    } else {
        outp = nullptr;
        spkp = base;
    }

    lsnn_kernel<<<BATCH, H>>>(x, enc_w, enc_b, ro_w, ro_b, A, Bv, outp, spkp);
}

// round 5
// speedup vs baseline: 1.5457x; 1.5457x over previous
#include <cuda_runtime.h>

#define BATCH 256
#define TSTEPS 4096
#define D 64
#define H 192
#define NCLS 10
#define BETA 0.9f
#define NW (TSTEPS / 2)

typedef unsigned long long ull;

// ---- packed f32x2 helpers (sm_100a). Each lane is an independent fp32 FMA
// with rn rounding -> per-lane bit-exact vs scalar __fmaf_rn sequence.
__device__ __forceinline__ ull pack2(float x, float y) {
    ull v; asm("mov.b64 %0, {%1, %2};" : "=l"(v) : "f"(x), "f"(y)); return v;
}
__device__ __forceinline__ void unpack2(ull v, float& x, float& y) {
    asm("mov.b64 {%0, %1}, %2;" : "=f"(x), "=f"(y) : "l"(v));
}
__device__ __forceinline__ void ffma2(ull& d, ull a, ull b) {
    asm("fma.rn.f32x2 %0, %1, %2, %0;" : "+l"(d) : "l"(a), "l"(b));
}

// Consumer sub-step: LIF update for 2 neurons (lanes), order identical to R4.
#define LIF_STEP(ACC, TIDX)                                                    \
    {                                                                          \
        float a0, a1; unpack2(ACC, a0, a1);                                    \
        float cur0 = __fadd_rn(a0, eb0);                                       \
        float cur1 = __fadd_rn(a1, eb1);                                       \
        mem0 = __fmaf_rn(BETA, mem0, cur0);                                    \
        mem1 = __fmaf_rn(BETA, mem1, cur1);                                    \
        float s0 = (__fadd_rn(mem0, -1.0f) > 0.f) ? 1.f : 0.f;                 \
        float s1 = (__fadd_rn(mem1, -1.0f) > 0.f) ? 1.f : 0.f;                 \
        rate0 = __fadd_rn(rate0, s0);                                          \
        rate1 = __fadd_rn(rate1, s1);                                          \
        *reinterpret_cast<float2*>(spkc + (size_t)(TIDX) * H) =                \
            make_float2(s0, s1);                                               \
        mem0 = __fmul_rn(mem0, __fadd_rn(1.0f, -s0));                          \
        mem1 = __fmul_rn(mem1, __fadd_rn(1.0f, -s1));                          \
    }

// Consumer window: two independent 64-deep sequential-k chains, interleaved
// for ILP. Per-accumulator k-order 0..63 preserved exactly.
#define CONS_CHAINS(SA, SB, ACCA, ACCB)                                        \
    {                                                                          \
        const ulonglong2* __restrict__ pa = (const ulonglong2*)(SA);           \
        const ulonglong2* __restrict__ pb = (const ulonglong2*)(SB);           \
        _Pragma("unroll")                                                      \
        for (int k = 0; k < D / 2; k++) {                                      \
            ulonglong2 va = pa[k];                                             \
            ulonglong2 vb = pb[k];                                             \
            ffma2(ACCA, regs[2 * k],     va.x);                                \
            ffma2(ACCB, regs[2 * k],     vb.x);                                \
            ffma2(ACCA, regs[2 * k + 1], va.y);                                \
            ffma2(ACCB, regs[2 * k + 1], vb.y);                                \
        }                                                                      \
    }

__global__ __launch_bounds__(128, 2)
void lsnn_kernel(const float* __restrict__ x,
                 const float* __restrict__ enc_w,
                 const float* __restrict__ enc_b,
                 const float* __restrict__ ro_w,
                 const float* __restrict__ ro_b,
                 const float* __restrict__ A,
                 const float* __restrict__ Bv,
                 float* __restrict__ out,     // [BATCH, NCLS] or null
                 float* __restrict__ spk)     // [BATCH, TSTEPS, H]
{
    // 4-slot ring of DUPLICATED state: sdup[slot][k] = {s_k, s_k} as u64.
    __shared__ __align__(16) ull sdup[4][D];
    __shared__ float srate[H];

    const int b = blockIdx.x;
    const int tid = threadIdx.x;
    const float* xb = x + (size_t)b * TSTEPS;

    // Role-shared register file: A2 rows (producer) or enc_w rows (consumer).
    ull regs[D];

    ull B2 = 0;                       // producer only
    float eb0 = 0.f, eb1 = 0.f;       // consumer only
    float mem0 = 0.f, mem1 = 0.f, rate0 = 0.f, rate1 = 0.f;
    float* spkc = nullptr;

    if (tid < 32) {
        // ---- producer init: thread j owns state elems 2j, 2j+1 ----
        const int j = tid;
#pragma unroll
        for (int k = 0; k < D; k++)
            regs[k] = pack2(A[(2 * j) * D + k], A[(2 * j + 1) * D + k]);
        B2 = pack2(Bv[2 * j], Bv[2 * j + 1]);
        sdup[0][2 * j] = 0ull;        // s_0 = 0 lives in slot 0
        sdup[0][2 * j + 1] = 0ull;
    } else {
        // ---- consumer init: thread c owns neurons 2c, 2c+1 ----
        const int c = tid - 32;
#pragma unroll
        for (int k = 0; k < D; k++)
            regs[k] = pack2(enc_w[(2 * c) * D + k], enc_w[(2 * c + 1) * D + k]);
        eb0 = enc_b[2 * c];
        eb1 = enc_b[2 * c + 1];
        spkc = spk + (size_t)b * TSTEPS * H + 2 * c;
    }
    __syncthreads();

    for (int w = 0; w < NW; w++) {
        const int t0 = 2 * w;
        if (tid < 32) {
            // ===== producer: s_{t0+1} then s_{t0+2} (2 dependent chains) ====
            const int j = tid;
            float2 uu = *reinterpret_cast<const float2*>(xb + t0);
            {
                const ulonglong2* sp = (const ulonglong2*)sdup[t0 & 3];
                ull acc = 0ull;
#pragma unroll
                for (int k = 0; k < D / 2; k++) {
                    ulonglong2 sv = sp[k];
                    ffma2(acc, regs[2 * k], sv.x);
                    ffma2(acc, regs[2 * k + 1], sv.y);
                }
                ffma2(acc, B2, pack2(uu.x, uu.x));   // + B*u (contracted fma)
                float lo, hi; unpack2(acc, lo, hi);
                ulonglong2 st; st.x = pack2(lo, lo); st.y = pack2(hi, hi);
                ((ulonglong2*)sdup[(t0 + 1) & 3])[j] = st;
            }
            __syncwarp();
            {
                const ulonglong2* sp = (const ulonglong2*)sdup[(t0 + 1) & 3];
                ull acc = 0ull;
#pragma unroll
                for (int k = 0; k < D / 2; k++) {
                    ulonglong2 sv = sp[k];
                    ffma2(acc, regs[2 * k], sv.x);
                    ffma2(acc, regs[2 * k + 1], sv.y);
                }
                ffma2(acc, B2, pack2(uu.y, uu.y));
                float lo, hi; unpack2(acc, lo, hi);
                ulonglong2 st; st.x = pack2(lo, lo); st.y = pack2(hi, hi);
                ((ulonglong2*)sdup[(t0 + 2) & 3])[j] = st;
            }
        } else if (w > 0) {
            // ===== consumer: steps t0-2 and t0-1 (states s_{t0-1}, s_{t0}) ==
            ull acca = 0ull, accb = 0ull;
            CONS_CHAINS(sdup[(t0 - 1) & 3], sdup[t0 & 3], acca, accb);
            LIF_STEP(acca, t0 - 2);
            LIF_STEP(accb, t0 - 1);
        }
        __syncthreads();
    }

    // ===== epilogue: consumer steps T-2, T-1 (states s_{T-1}, s_T) =====
    if (tid >= 32) {
        ull acca = 0ull, accb = 0ull;
        CONS_CHAINS(sdup[(TSTEPS - 1) & 3], sdup[TSTEPS & 3], acca, accb);
        LIF_STEP(acca, TSTEPS - 2);
        LIF_STEP(accb, TSTEPS - 1);
        const int c = tid - 32;
        srate[2 * c]     = __fmul_rn(rate0, 1.0f / (float)TSTEPS);
        srate[2 * c + 1] = __fmul_rn(rate1, 1.0f / (float)TSTEPS);
    }
    __syncthreads();

    // ---- readout: sequential-k fmaf chain, separate bias add (as R4) ----
    if (tid < NCLS && out != nullptr) {
        float acc = 0.f;
        const float* rw = ro_w + tid * H;
#pragma unroll
        for (int h = 0; h < H; h++)
            acc = __fmaf_rn(rw[h], srate[h], acc);
        out[b * NCLS + tid] = __fadd_rn(acc, ro_b[tid]);
    }
}

extern "C" void kernel_launch(void* const* d_in, const int* in_sizes, int n_in,
                              void* d_out, int out_size) {
    const float* x     = (const float*)d_in[0];
    const float* enc_w = (const float*)d_in[1];
    const float* enc_b = (const float*)d_in[2];
    const float* ro_w  = (const float*)d_in[3];
    const float* ro_b  = (const float*)d_in[4];
    const float* A     = (const float*)d_in[5];
    const float* Bv    = (const float*)d_in[6];

    float* base = (float*)d_out;
    const long long spkElems = (long long)BATCH * TSTEPS * H;   // 201326592
    const long long outElems = (long long)BATCH * NCLS;          // 2560

    float* outp;
    float* spkp;
    if ((long long)out_size >= spkElems + outElems) {
        outp = base;
        spkp = base + outElems;
    } else {
        outp = nullptr;
        spkp = base;
    }

    lsnn_kernel<<<BATCH, 128>>>(x, enc_w, enc_b, ro_w, ro_b, A, Bv, outp, spkp);
}